// round 7
// baseline (speedup 1.0000x reference)
#include <cuda_runtime.h>
#include <cstdint>

// ============================================================================
// MIPT cell, sm_103-portable path (compute_103 virtual arch: no tcgen05).
// tf32 mma.sync GEMM, 64x64 warp tiles (2x4 warps, CTA 128x256), ldmatrix
// fragment loads, SINGLE-buffered fragments (register budget ~185, no spills):
//   proj = e_t @ [W_p; W_th; W_r; W_i]^T + b   (B=8192, D=2048)
// fused with sigmoid / sincos rotation / blend epilogue.
// ============================================================================

#define D_DIM 2048
#define B_DIM 8192
#define BM 128
#define BN 256              // 64 cols x 4 segments
#define BK 32
#define NITER (D_DIM / BK)  // 64
#define STAGES 3
#define PADK 36             // padded smem row stride (floats); 144B rows
#define STAGE_A_BYTES (BM * PADK * 4)            // 18432
#define STAGE_B_BYTES (BN * PADK * 4)            // 36864
#define STAGE_BYTES (STAGE_A_BYTES + STAGE_B_BYTES)  // 55296
#define SMEM_MAIN (STAGES * STAGE_BYTES)         // 165888
#define EPI_STRIDE 260

// ---------------------------------------------------------------------------
// Scratch: tf32-RNA-rounded operands (__device__ globals; alloc-free rule)
// ---------------------------------------------------------------------------
__device__ float g_A[(size_t)B_DIM * D_DIM];        // 64 MB
__device__ float g_W[(size_t)4 * D_DIM * D_DIM];    // 64 MB

__device__ __forceinline__ uint32_t smem_u32(const void* p) {
    uint32_t a;
    asm("{ .reg .u64 t; cvta.to.shared.u64 t, %1; cvt.u32.u64 %0, t; }" : "=r"(a) : "l"(p));
    return a;
}
__device__ __forceinline__ float tf32_rna(float x) {
    uint32_t u;
    asm("cvt.rna.tf32.f32 %0, %1;" : "=r"(u) : "f"(x));
    return __uint_as_float(u);
}
__device__ __forceinline__ void cp_async16(uint32_t dst, const void* src) {
    asm volatile("cp.async.cg.shared.global [%0], [%1], 16;" :: "r"(dst), "l"(src));
}
__device__ __forceinline__ void mma_tf32(float* d, const uint32_t* a, const uint32_t* b) {
    asm volatile(
        "mma.sync.aligned.m16n8k8.row.col.f32.tf32.tf32.f32 "
        "{%0,%1,%2,%3}, {%4,%5,%6,%7}, {%8,%9}, {%0,%1,%2,%3};"
        : "+f"(d[0]), "+f"(d[1]), "+f"(d[2]), "+f"(d[3])
        : "r"(a[0]), "r"(a[1]), "r"(a[2]), "r"(a[3]), "r"(b[0]), "r"(b[1]));
}
__device__ __forceinline__ void ldsm_x4(uint32_t* r, uint32_t addr) {
    asm volatile("ldmatrix.sync.aligned.m8n8.x4.shared.b16 {%0,%1,%2,%3}, [%4];"
                 : "=r"(r[0]), "=r"(r[1]), "=r"(r[2]), "=r"(r[3]) : "r"(addr));
}

// ---------------------------------------------------------------------------
// Prepass kernels: fp32 -> nearest tf32 (removes HW truncation bias)
// ---------------------------------------------------------------------------
__global__ void tf32_round_kernel(const float4* __restrict__ src,
                                  float4* __restrict__ dst, int n4) {
    int stride = gridDim.x * blockDim.x;
    for (int i = blockIdx.x * blockDim.x + threadIdx.x; i < n4; i += stride) {
        float4 v = src[i];
        v.x = tf32_rna(v.x); v.y = tf32_rna(v.y);
        v.z = tf32_rna(v.z); v.w = tf32_rna(v.w);
        dst[i] = v;
    }
}
__global__ void tf32_round4_kernel(const float4* __restrict__ s0,
                                   const float4* __restrict__ s1,
                                   const float4* __restrict__ s2,
                                   const float4* __restrict__ s3,
                                   float4* __restrict__ dst, int n4) {
    const float4* src = (blockIdx.y == 0) ? s0 : (blockIdx.y == 1) ? s1
                       : (blockIdx.y == 2) ? s2 : s3;
    float4* d = dst + (size_t)blockIdx.y * n4;
    int stride = gridDim.x * blockDim.x;
    for (int i = blockIdx.x * blockDim.x + threadIdx.x; i < n4; i += stride) {
        float4 v = src[i];
        v.x = tf32_rna(v.x); v.y = tf32_rna(v.y);
        v.z = tf32_rna(v.z); v.w = tf32_rna(v.w);
        d[i] = v;
    }
}

// ---------------------------------------------------------------------------
// Fused GEMM + epilogue
// ---------------------------------------------------------------------------
__global__ void __launch_bounds__(256, 1)
mipt_kernel(const float* __restrict__ gA, const float* __restrict__ gW,
            const float* __restrict__ h_prev,
            const float* __restrict__ b_p, const float* __restrict__ b_th,
            const float* __restrict__ b_r, const float* __restrict__ b_i,
            float* __restrict__ out) {
    extern __shared__ float sm[];
    const int tid = threadIdx.x;
    const int bx = blockIdx.x;
    const int mt = bx & 63;          // m-tile (64)
    const int nt = bx >> 6;          // n-tile (32; 64 cols per segment)
    const uint32_t sbase = smem_u32(sm);

    const int wid = tid >> 5, lane = tid & 31;
    const int g = lane >> 2, tg = lane & 3;
    const int wm = (wid & 1) * 64;   // warp m offset (2 m-warps)
    const int wn = (wid >> 1) * 64;  // warp n offset (4 n-warps)

    // ldmatrix per-lane base offsets (within a stage)
    const uint32_t aoff =
        ((uint32_t)((wm + (lane & 15)) * PADK + ((lane >> 4) << 2))) * 4u;
    const int rowB = wn + (lane & 7) + ((lane >> 4) << 3);
    const uint32_t boff =
        ((uint32_t)(rowB * PADK + (((lane >> 3) & 1) << 2))) * 4u;

    // ---- async stage loader: A [128 x 32] + B [256 x 32] = 3072 chunks ----
    auto load_stage = [&](int s, int k0) {
        const uint32_t smA = sbase + s * STAGE_BYTES;
        #pragma unroll
        for (int r = 0; r < 12; r++) {
            const int ch = tid + r * 256;         // 0..3071
            const int row = ch >> 3, q = ch & 7;  // 8 x 16B chunks per 128B row
            if (row < BM) {
                const float* ga = gA + (size_t)(mt * 128 + row) * D_DIM + k0 + q * 4;
                cp_async16(smA + row * (PADK * 4) + q * 16, ga);
            } else {
                const int br = row - BM;          // 0..255
                const int j = br >> 6, c = br & 63;
                const float* gb = gW + (size_t)j * (D_DIM * D_DIM)
                                     + (size_t)(nt * 64 + c) * D_DIM + k0 + q * 4;
                cp_async16(smA + STAGE_A_BYTES + br * (PADK * 4) + q * 16, gb);
            }
        }
        asm volatile("cp.async.commit_group;");
    };

    float acc[4][8][4] = {};          // [mi][ni][regs] : 64x64 warp tile
    uint32_t af[4][4];                // single-buffered fragments
    uint32_t bf[4][4];

    load_stage(0, 0);
    load_stage(1, BK);

    for (int it = 0; it < NITER; it++) {
        asm volatile("cp.async.wait_group %0;" :: "n"(STAGES - 2));
        __syncthreads();
        const int cs = it % STAGES;
        const uint32_t sA = sbase + (uint32_t)cs * STAGE_BYTES;
        const uint32_t sB = sA + STAGE_A_BYTES;

        // get next stage's GMEM loads in flight before consuming this one
        if (it + STAGES - 1 < NITER)
            load_stage((it + STAGES - 1) % STAGES, (it + STAGES - 1) * BK);

        #pragma unroll
        for (int kk = 0; kk < 4; kk++) {
            const uint32_t ko = (uint32_t)kk * 32u;
            #pragma unroll
            for (int mi = 0; mi < 4; mi++)
                ldsm_x4(af[mi], sA + aoff + (uint32_t)mi * (16u * PADK * 4u) + ko);
            #pragma unroll
            for (int nb = 0; nb < 4; nb++)
                ldsm_x4(bf[nb], sB + boff + (uint32_t)nb * (16u * PADK * 4u) + ko);
            #pragma unroll
            for (int mi = 0; mi < 4; mi++)
                #pragma unroll
                for (int nb = 0; nb < 4; nb++) {
                    mma_tf32(acc[mi][2 * nb],     af[mi], &bf[nb][0]);
                    mma_tf32(acc[mi][2 * nb + 1], af[mi], &bf[nb][2]);
                }
        }
    }

    // ---- stage accumulators through smem: thread gathers (p,th,re,im) ----
    asm volatile("cp.async.wait_group 0;");
    __syncthreads();
    float* epi = sm;   // 128 x EPI_STRIDE (133 KB <= SMEM_MAIN)
    #pragma unroll
    for (int mi = 0; mi < 4; mi++)
        #pragma unroll
        for (int ni = 0; ni < 8; ni++) {
            const int r = wm + mi * 16 + g;
            const int n = wn + ni * 8 + 2 * tg;
            epi[r * EPI_STRIDE + n]           = acc[mi][ni][0];
            epi[r * EPI_STRIDE + n + 1]       = acc[mi][ni][1];
            epi[(r + 8) * EPI_STRIDE + n]     = acc[mi][ni][2];
            epi[(r + 8) * EPI_STRIDE + n + 1] = acc[mi][ni][3];
        }
    __syncthreads();

    // ---- fused epilogue: sigmoid gate + rotation + blend ----
    const int rowt = tid >> 4;            // 0..15
    const int cb = (tid & 15) * 4;        // 0..60
    const int ng = nt * 64 + cb;
    const float4 bp = *(const float4*)&b_p[ng];
    const float4 bt = *(const float4*)&b_th[ng];
    const float4 br = *(const float4*)&b_r[ng];
    const float4 bi = *(const float4*)&b_i[ng];

    #pragma unroll
    for (int rep = 0; rep < 8; rep++) {
        const int m = rep * 16 + rowt;
        const size_t gm = (size_t)(mt * 128 + m);
        const float4 pl = *(const float4*)&epi[m * EPI_STRIDE + 0 * 64 + cb];
        const float4 th = *(const float4*)&epi[m * EPI_STRIDE + 1 * 64 + cb];
        const float4 xr = *(const float4*)&epi[m * EPI_STRIDE + 2 * 64 + cb];
        const float4 xi = *(const float4*)&epi[m * EPI_STRIDE + 3 * 64 + cb];
        const float4 hr = *(const float4*)&h_prev[gm * (2 * D_DIM) + ng];
        const float4 hi = *(const float4*)&h_prev[gm * (2 * D_DIM) + D_DIM + ng];

        float plv[4] = {pl.x + bp.x, pl.y + bp.y, pl.z + bp.z, pl.w + bp.w};
        float thv[4] = {th.x + bt.x, th.y + bt.y, th.z + bt.z, th.w + bt.w};
        float xrv[4] = {xr.x + br.x, xr.y + br.y, xr.z + br.z, xr.w + br.w};
        float xiv[4] = {xi.x + bi.x, xi.y + bi.y, xi.z + bi.z, xi.w + bi.w};
        float hrv[4] = {hr.x, hr.y, hr.z, hr.w};
        float hiv[4] = {hi.x, hi.y, hi.z, hi.w};
        float ore[4], oim[4];
        #pragma unroll
        for (int c = 0; c < 4; c++) {
            const float p = 1.0f / (1.0f + __expf(-plv[c]));
            float sn, cs;
            __sincosf(thv[c], &sn, &cs);
            const float rre = cs * hrv[c] - sn * hiv[c];
            const float rim = sn * hrv[c] + cs * hiv[c];
            ore[c] = rre + p * (xrv[c] - rre);
            oim[c] = rim + p * (xiv[c] - rim);
        }
        *(float4*)&out[gm * (2 * D_DIM) + ng] =
            make_float4(ore[0], ore[1], ore[2], ore[3]);
        *(float4*)&out[gm * (2 * D_DIM) + D_DIM + ng] =
            make_float4(oim[0], oim[1], oim[2], oim[3]);
    }
}

// ---------------------------------------------------------------------------
// Host
// ---------------------------------------------------------------------------
extern "C" void kernel_launch(void* const* d_in, const int* in_sizes, int n_in,
                              void* d_out, int out_size) {
    const float* e_t    = (const float*)d_in[0];
    const float* h_prev = (const float*)d_in[1];
    const float* W_p    = (const float*)d_in[2];
    const float* b_p    = (const float*)d_in[3];
    const float* W_th   = (const float*)d_in[4];
    const float* b_th   = (const float*)d_in[5];
    const float* W_r    = (const float*)d_in[6];
    const float* b_r    = (const float*)d_in[7];
    const float* W_i    = (const float*)d_in[8];
    const float* b_i    = (const float*)d_in[9];
    float* out = (float*)d_out;

    float* sA = nullptr; float* sW = nullptr;
    cudaGetSymbolAddress((void**)&sA, g_A);
    cudaGetSymbolAddress((void**)&sW, g_W);

    const size_t nA = (size_t)B_DIM * D_DIM;
    const size_t nW = (size_t)D_DIM * D_DIM;
    tf32_round_kernel<<<2048, 256>>>((const float4*)e_t, (float4*)sA, (int)(nA / 4));
    tf32_round4_kernel<<<dim3(512, 4), 256>>>(
        (const float4*)W_p, (const float4*)W_th, (const float4*)W_r,
        (const float4*)W_i, (float4*)sW, (int)(nW / 4));

    cudaFuncSetAttribute(mipt_kernel, cudaFuncAttributeMaxDynamicSharedMemorySize,
                         SMEM_MAIN);
    // grid: nt-major so a wave shares W tiles; A stays L2-resident
    mipt_kernel<<<64 * 32, 256, SMEM_MAIN>>>(sA, sW, h_prev,
                                             b_p, b_th, b_r, b_i, out);
}

// round 8
// speedup vs baseline: 1.9226x; 1.9226x over previous
#include <cuda_runtime.h>
#include <cuda_fp16.h>
#include <cstdint>

// ============================================================================
// MIPT cell, sm_103-portable path (compute_103 virtual arch: no tcgen05).
// fp16 mma.sync m16n8k16 GEMM (same 10-bit mantissa as tf32, 2x MACs/instr),
// 64x64 warp tiles (2x4 warps, CTA 128x256), ldmatrix + double-buffered frags:
//   proj = e_t @ [W_p; W_th; W_r; W_i]^T + b   (B=8192, D=2048)
// fused with sigmoid / sincos rotation / blend epilogue.
// ============================================================================

#define D_DIM 2048
#define B_DIM 8192
#define BM 128
#define BN 256              // 64 cols x 4 segments
#define BK 64               // K halfs per stage (128B data rows)
#define NITER (D_DIM / BK)  // 32
#define STAGES 3
#define PADKH 72            // padded smem row stride in halfs; 144B rows
#define ROWB 144            // row bytes
#define STAGE_A_BYTES (BM * ROWB)                // 18432
#define STAGE_B_BYTES (BN * ROWB)                // 36864
#define STAGE_BYTES (STAGE_A_BYTES + STAGE_B_BYTES)  // 55296
#define SMEM_MAIN (STAGES * STAGE_BYTES)         // 165888
#define EPI_STRIDE 260

// ---------------------------------------------------------------------------
// Scratch: fp16-rounded operands (__device__ globals; alloc-free rule)
// ---------------------------------------------------------------------------
__device__ __half g_Ah[(size_t)B_DIM * D_DIM];        // 32 MB
__device__ __half g_Wh[(size_t)4 * D_DIM * D_DIM];    // 32 MB

__device__ __forceinline__ uint32_t smem_u32(const void* p) {
    uint32_t a;
    asm("{ .reg .u64 t; cvta.to.shared.u64 t, %1; cvt.u32.u64 %0, t; }" : "=r"(a) : "l"(p));
    return a;
}
__device__ __forceinline__ void cp_async16(uint32_t dst, const void* src) {
    asm volatile("cp.async.cg.shared.global [%0], [%1], 16;" :: "r"(dst), "l"(src));
}
__device__ __forceinline__ void mma_f16(float* d, const uint32_t* a, const uint32_t* b) {
    asm volatile(
        "mma.sync.aligned.m16n8k16.row.col.f32.f16.f16.f32 "
        "{%0,%1,%2,%3}, {%4,%5,%6,%7}, {%8,%9}, {%0,%1,%2,%3};"
        : "+f"(d[0]), "+f"(d[1]), "+f"(d[2]), "+f"(d[3])
        : "r"(a[0]), "r"(a[1]), "r"(a[2]), "r"(a[3]), "r"(b[0]), "r"(b[1]));
}
__device__ __forceinline__ void ldsm_x4(uint32_t* r, uint32_t addr) {
    asm volatile("ldmatrix.sync.aligned.m8n8.x4.shared.b16 {%0,%1,%2,%3}, [%4];"
                 : "=r"(r[0]), "=r"(r[1]), "=r"(r[2]), "=r"(r[3]) : "r"(addr));
}

// ---------------------------------------------------------------------------
// Prepass: fp32 -> fp16 (RN)
// ---------------------------------------------------------------------------
__global__ void f2h_kernel(const float4* __restrict__ src,
                           __half2* __restrict__ dst, int n4) {
    int stride = gridDim.x * blockDim.x;
    for (int i = blockIdx.x * blockDim.x + threadIdx.x; i < n4; i += stride) {
        float4 v = src[i];
        dst[2 * i]     = __floats2half2_rn(v.x, v.y);
        dst[2 * i + 1] = __floats2half2_rn(v.z, v.w);
    }
}
__global__ void f2h4_kernel(const float4* __restrict__ s0,
                            const float4* __restrict__ s1,
                            const float4* __restrict__ s2,
                            const float4* __restrict__ s3,
                            __half2* __restrict__ dst, int n4) {
    const float4* src = (blockIdx.y == 0) ? s0 : (blockIdx.y == 1) ? s1
                       : (blockIdx.y == 2) ? s2 : s3;
    __half2* d = dst + (size_t)blockIdx.y * n4 * 2;
    int stride = gridDim.x * blockDim.x;
    for (int i = blockIdx.x * blockDim.x + threadIdx.x; i < n4; i += stride) {
        float4 v = src[i];
        d[2 * i]     = __floats2half2_rn(v.x, v.y);
        d[2 * i + 1] = __floats2half2_rn(v.z, v.w);
    }
}

// ---------------------------------------------------------------------------
// Fused GEMM + epilogue
// ---------------------------------------------------------------------------
__global__ void __launch_bounds__(256, 1)
mipt_kernel(const __half* __restrict__ gA, const __half* __restrict__ gW,
            const float* __restrict__ h_prev,
            const float* __restrict__ b_p, const float* __restrict__ b_th,
            const float* __restrict__ b_r, const float* __restrict__ b_i,
            float* __restrict__ out) {
    extern __shared__ float sm[];
    const int tid = threadIdx.x;
    const int bx = blockIdx.x;
    const int mt = bx & 63;          // m-tile (64)
    const int nt = bx >> 6;          // n-tile (32; 64 cols per segment)
    const uint32_t sbase = smem_u32(sm);

    const int wid = tid >> 5, lane = tid & 31;
    const int g = lane >> 2, tg = lane & 3;
    const int wm = (wid & 1) * 64;   // warp m offset (2 m-warps)
    const int wn = (wid >> 1) * 64;  // warp n offset (4 n-warps)

    // ldmatrix per-lane base byte offsets (within a stage)
    // A (m16 frag): lanes0-15 rows, lanes16-31 same rows +16B (k8-15)
    const uint32_t aoff =
        (uint32_t)((wm + (lane & 15)) * ROWB) + ((uint32_t)(lane >> 4) << 4);
    // B (two n8 blocks): lanes0-7 rows n..n+7 k0; 8-15 +16B; 16-23 rows n+8; 24-31 +16B
    const int rowB = wn + (lane & 7) + ((lane >> 4) << 3);
    const uint32_t boff =
        (uint32_t)(rowB * ROWB) + (((uint32_t)(lane >> 3) & 1u) << 4);

    // ---- async stage loader: A [128 x 64h] + B [256 x 64h] = 3072 chunks ----
    auto load_stage = [&](int s, int k0) {
        const uint32_t smA = sbase + s * STAGE_BYTES;
        #pragma unroll
        for (int r = 0; r < 12; r++) {
            const int ch = tid + r * 256;         // 0..3071
            const int row = ch >> 3, q = ch & 7;  // 8 x 16B chunks (8 halfs each)
            if (row < BM) {
                const __half* ga = gA + (size_t)(mt * 128 + row) * D_DIM + k0 + q * 8;
                cp_async16(smA + row * ROWB + q * 16, ga);
            } else {
                const int br = row - BM;          // 0..255
                const int j = br >> 6, c = br & 63;
                const __half* gb = gW + (size_t)j * (D_DIM * D_DIM)
                                      + (size_t)(nt * 64 + c) * D_DIM + k0 + q * 8;
                cp_async16(smA + STAGE_A_BYTES + br * ROWB + q * 16, gb);
            }
        }
        asm volatile("cp.async.commit_group;");
    };

    float acc[4][8][4] = {};          // [mi][ni][regs] : 64x64 warp tile
    uint32_t af[2][4][4];             // [buf][mi][regs]
    uint32_t bf[2][4][4];             // [buf][nb][regs] (nb -> ni=2nb,2nb+1)

    load_stage(0, 0);
    load_stage(1, BK);

    for (int it = 0; it < NITER; it++) {
        asm volatile("cp.async.wait_group %0;" :: "n"(STAGES - 2));
        __syncthreads();
        const int cs = it % STAGES;
        const uint32_t sA = sbase + (uint32_t)cs * STAGE_BYTES;
        const uint32_t sB = sA + STAGE_A_BYTES;

        // prefetch kk=0 fragments before the cp.async issue burst
        #pragma unroll
        for (int mi = 0; mi < 4; mi++)
            ldsm_x4(af[0][mi], sA + aoff + (uint32_t)mi * (16u * ROWB));
        #pragma unroll
        for (int nb = 0; nb < 4; nb++)
            ldsm_x4(bf[0][nb], sB + boff + (uint32_t)nb * (16u * ROWB));

        if (it + STAGES - 1 < NITER)
            load_stage((it + STAGES - 1) % STAGES, (it + STAGES - 1) * BK);

        #pragma unroll
        for (int kk = 0; kk < 4; kk++) {          // 4 x k16 per stage
            const int cur = kk & 1, nxt = cur ^ 1;
            if (kk < 3) {   // prefetch next kk fragments (+32B per k16 step)
                const uint32_t ko = (uint32_t)(kk + 1) * 32u;
                #pragma unroll
                for (int mi = 0; mi < 4; mi++)
                    ldsm_x4(af[nxt][mi],
                            sA + aoff + (uint32_t)mi * (16u * ROWB) + ko);
                #pragma unroll
                for (int nb = 0; nb < 4; nb++)
                    ldsm_x4(bf[nxt][nb],
                            sB + boff + (uint32_t)nb * (16u * ROWB) + ko);
            }
            #pragma unroll
            for (int mi = 0; mi < 4; mi++)
                #pragma unroll
                for (int nb = 0; nb < 4; nb++) {
                    mma_f16(acc[mi][2 * nb],     af[cur][mi], &bf[cur][nb][0]);
                    mma_f16(acc[mi][2 * nb + 1], af[cur][mi], &bf[cur][nb][2]);
                }
        }
    }

    // ---- stage accumulators through smem: thread gathers (p,th,re,im) ----
    asm volatile("cp.async.wait_group 0;");
    __syncthreads();
    float* epi = sm;   // 128 x EPI_STRIDE (133 KB <= SMEM_MAIN)
    #pragma unroll
    for (int mi = 0; mi < 4; mi++)
        #pragma unroll
        for (int ni = 0; ni < 8; ni++) {
            const int r = wm + mi * 16 + g;
            const int n = wn + ni * 8 + 2 * tg;
            epi[r * EPI_STRIDE + n]           = acc[mi][ni][0];
            epi[r * EPI_STRIDE + n + 1]       = acc[mi][ni][1];
            epi[(r + 8) * EPI_STRIDE + n]     = acc[mi][ni][2];
            epi[(r + 8) * EPI_STRIDE + n + 1] = acc[mi][ni][3];
        }
    __syncthreads();

    // ---- fused epilogue: sigmoid gate + rotation + blend ----
    const int rowt = tid >> 4;            // 0..15
    const int cb = (tid & 15) * 4;        // 0..60
    const int ng = nt * 64 + cb;
    const float4 bp = *(const float4*)&b_p[ng];
    const float4 bt = *(const float4*)&b_th[ng];
    const float4 br = *(const float4*)&b_r[ng];
    const float4 bi = *(const float4*)&b_i[ng];

    #pragma unroll
    for (int rep = 0; rep < 8; rep++) {
        const int m = rep * 16 + rowt;
        const size_t gm = (size_t)(mt * 128 + m);
        const float4 pl = *(const float4*)&epi[m * EPI_STRIDE + 0 * 64 + cb];
        const float4 th = *(const float4*)&epi[m * EPI_STRIDE + 1 * 64 + cb];
        const float4 xr = *(const float4*)&epi[m * EPI_STRIDE + 2 * 64 + cb];
        const float4 xi = *(const float4*)&epi[m * EPI_STRIDE + 3 * 64 + cb];
        const float4 hr = *(const float4*)&h_prev[gm * (2 * D_DIM) + ng];
        const float4 hi = *(const float4*)&h_prev[gm * (2 * D_DIM) + D_DIM + ng];

        float plv[4] = {pl.x + bp.x, pl.y + bp.y, pl.z + bp.z, pl.w + bp.w};
        float thv[4] = {th.x + bt.x, th.y + bt.y, th.z + bt.z, th.w + bt.w};
        float xrv[4] = {xr.x + br.x, xr.y + br.y, xr.z + br.z, xr.w + br.w};
        float xiv[4] = {xi.x + bi.x, xi.y + bi.y, xi.z + bi.z, xi.w + bi.w};
        float hrv[4] = {hr.x, hr.y, hr.z, hr.w};
        float hiv[4] = {hi.x, hi.y, hi.z, hi.w};
        float ore[4], oim[4];
        #pragma unroll
        for (int c = 0; c < 4; c++) {
            const float p = 1.0f / (1.0f + __expf(-plv[c]));
            float sn, cs;
            __sincosf(thv[c], &sn, &cs);
            const float rre = cs * hrv[c] - sn * hiv[c];
            const float rim = sn * hrv[c] + cs * hiv[c];
            ore[c] = rre + p * (xrv[c] - rre);
            oim[c] = rim + p * (xiv[c] - rim);
        }
        *(float4*)&out[gm * (2 * D_DIM) + ng] =
            make_float4(ore[0], ore[1], ore[2], ore[3]);
        *(float4*)&out[gm * (2 * D_DIM) + D_DIM + ng] =
            make_float4(oim[0], oim[1], oim[2], oim[3]);
    }
}

// ---------------------------------------------------------------------------
// Host
// ---------------------------------------------------------------------------
extern "C" void kernel_launch(void* const* d_in, const int* in_sizes, int n_in,
                              void* d_out, int out_size) {
    const float* e_t    = (const float*)d_in[0];
    const float* h_prev = (const float*)d_in[1];
    const float* W_p    = (const float*)d_in[2];
    const float* b_p    = (const float*)d_in[3];
    const float* W_th   = (const float*)d_in[4];
    const float* b_th   = (const float*)d_in[5];
    const float* W_r    = (const float*)d_in[6];
    const float* b_r    = (const float*)d_in[7];
    const float* W_i    = (const float*)d_in[8];
    const float* b_i    = (const float*)d_in[9];
    float* out = (float*)d_out;

    __half* sA = nullptr; __half* sW = nullptr;
    cudaGetSymbolAddress((void**)&sA, g_Ah);
    cudaGetSymbolAddress((void**)&sW, g_Wh);

    const size_t nA = (size_t)B_DIM * D_DIM;
    const size_t nW = (size_t)D_DIM * D_DIM;
    f2h_kernel<<<2048, 256>>>((const float4*)e_t, (__half2*)sA, (int)(nA / 4));
    f2h4_kernel<<<dim3(512, 4), 256>>>(
        (const float4*)W_p, (const float4*)W_th, (const float4*)W_r,
        (const float4*)W_i, (__half2*)sW, (int)(nW / 4));

    cudaFuncSetAttribute(mipt_kernel, cudaFuncAttributeMaxDynamicSharedMemorySize,
                         SMEM_MAIN);
    // grid: nt-major so a wave shares W tiles; A stays L2-resident
    mipt_kernel<<<64 * 32, 256, SMEM_MAIN>>>(sA, sW, h_prev,
                                             b_p, b_th, b_r, b_i, out);
}

// round 10
// speedup vs baseline: 2.0305x; 1.0561x over previous
#include <cuda_runtime.h>
#include <cuda_fp16.h>
#include <cstdint>

// ============================================================================
// MIPT cell, sm_103-portable path (compute_103 virtual arch: no tcgen05).
// fp16 mma.sync m16n8k16 GEMM, CTA 128x256, 16 warps (4x4), warp tile 32x64:
// 4 warps/SMSP to hide MMA-pipe + LDSM latency.
//   proj = e_t @ [W_p; W_th; W_r; W_i]^T + b   (B=8192, D=2048)
// fused with sigmoid / sincos rotation / blend epilogue.
// ============================================================================

#define D_DIM 2048
#define B_DIM 8192
#define BM 128
#define BN 256              // 64 cols x 4 segments
#define BK 64               // K halfs per stage (128B data rows)
#define NITER (D_DIM / BK)  // 32
#define STAGES 3
#define ROWB 144            // padded row bytes (128B data + 16B)
#define STAGE_A_BYTES (BM * ROWB)                // 18432
#define STAGE_B_BYTES (BN * ROWB)                // 36864
#define STAGE_BYTES (STAGE_A_BYTES + STAGE_B_BYTES)  // 55296
#define SMEM_MAIN (STAGES * STAGE_BYTES)         // 165888
#define EPI_STRIDE 260
#define NTHREADS 512

// ---------------------------------------------------------------------------
// Scratch: fp16-rounded operands (__device__ globals; alloc-free rule)
// ---------------------------------------------------------------------------
__device__ __half g_Ah[(size_t)B_DIM * D_DIM];        // 32 MB
__device__ __half g_Wh[(size_t)4 * D_DIM * D_DIM];    // 32 MB

__device__ __forceinline__ uint32_t smem_u32(const void* p) {
    uint32_t a;
    asm("{ .reg .u64 t; cvta.to.shared.u64 t, %1; cvt.u32.u64 %0, t; }" : "=r"(a) : "l"(p));
    return a;
}
__device__ __forceinline__ void cp_async16(uint32_t dst, const void* src) {
    asm volatile("cp.async.cg.shared.global [%0], [%1], 16;" :: "r"(dst), "l"(src));
}
__device__ __forceinline__ void mma_f16(float* d, const uint32_t* a, const uint32_t* b) {
    asm volatile(
        "mma.sync.aligned.m16n8k16.row.col.f32.f16.f16.f32 "
        "{%0,%1,%2,%3}, {%4,%5,%6,%7}, {%8,%9}, {%0,%1,%2,%3};"
        : "+f"(d[0]), "+f"(d[1]), "+f"(d[2]), "+f"(d[3])
        : "r"(a[0]), "r"(a[1]), "r"(a[2]), "r"(a[3]), "r"(b[0]), "r"(b[1]));
}
__device__ __forceinline__ void ldsm_x4(uint32_t* r, uint32_t addr) {
    asm volatile("ldmatrix.sync.aligned.m8n8.x4.shared.b16 {%0,%1,%2,%3}, [%4];"
                 : "=r"(r[0]), "=r"(r[1]), "=r"(r[2]), "=r"(r[3]) : "r"(addr));
}

// ---------------------------------------------------------------------------
// Prepass: fp32 -> fp16 (RN)
// ---------------------------------------------------------------------------
__global__ void f2h_kernel(const float4* __restrict__ src,
                           __half2* __restrict__ dst, int n4) {
    int stride = gridDim.x * blockDim.x;
    for (int i = blockIdx.x * blockDim.x + threadIdx.x; i < n4; i += stride) {
        float4 v = src[i];
        dst[2 * i]     = __floats2half2_rn(v.x, v.y);
        dst[2 * i + 1] = __floats2half2_rn(v.z, v.w);
    }
}
__global__ void f2h4_kernel(const float4* __restrict__ s0,
                            const float4* __restrict__ s1,
                            const float4* __restrict__ s2,
                            const float4* __restrict__ s3,
                            __half2* __restrict__ dst, int n4) {
    const float4* src = (blockIdx.y == 0) ? s0 : (blockIdx.y == 1) ? s1
                       : (blockIdx.y == 2) ? s2 : s3;
    __half2* d = dst + (size_t)blockIdx.y * n4 * 2;
    int stride = gridDim.x * blockDim.x;
    for (int i = blockIdx.x * blockDim.x + threadIdx.x; i < n4; i += stride) {
        float4 v = src[i];
        d[2 * i]     = __floats2half2_rn(v.x, v.y);
        d[2 * i + 1] = __floats2half2_rn(v.z, v.w);
    }
}

// ---------------------------------------------------------------------------
// Fused GEMM + epilogue
// ---------------------------------------------------------------------------
__global__ void __launch_bounds__(NTHREADS, 1)
mipt_kernel(const __half* __restrict__ gA, const __half* __restrict__ gW,
            const float* __restrict__ h_prev,
            const float* __restrict__ b_p, const float* __restrict__ b_th,
            const float* __restrict__ b_r, const float* __restrict__ b_i,
            float* __restrict__ out) {
    extern __shared__ float sm[];
    const int tid = threadIdx.x;
    const int bx = blockIdx.x;
    const int mt = bx & 63;          // m-tile (64)
    const int nt = bx >> 6;          // n-tile (32; 64 cols per segment)
    const uint32_t sbase = smem_u32(sm);

    const int wid = tid >> 5, lane = tid & 31;
    const int g = lane >> 2, tg = lane & 3;
    const int wm = (wid & 3) * 32;   // warp m offset (4 m-warps)
    const int wn = (wid >> 2) * 64;  // warp n offset (4 n-warps)

    // ldmatrix per-lane base byte offsets (within a stage)
    const uint32_t aoff =
        (uint32_t)((wm + (lane & 15)) * ROWB) + ((uint32_t)(lane >> 4) << 4);
    const int rowB = wn + (lane & 7) + ((lane >> 4) << 3);
    const uint32_t boff =
        (uint32_t)(rowB * ROWB) + (((uint32_t)(lane >> 3) & 1u) << 4);

    // ---- async stage loader: A [128 x 64h] + B [256 x 64h] = 3072 chunks ----
    auto load_stage = [&](int s, int k0) {
        const uint32_t smA = sbase + s * STAGE_BYTES;
        #pragma unroll
        for (int r = 0; r < 6; r++) {
            const int ch = tid + r * NTHREADS;    // 0..3071
            const int row = ch >> 3, q = ch & 7;  // 8 x 16B chunks (8 halfs each)
            if (row < BM) {
                const __half* ga = gA + (size_t)(mt * 128 + row) * D_DIM + k0 + q * 8;
                cp_async16(smA + row * ROWB + q * 16, ga);
            } else {
                const int br = row - BM;          // 0..255
                const int j = br >> 6, c = br & 63;
                const __half* gb = gW + (size_t)j * (D_DIM * D_DIM)
                                      + (size_t)(nt * 64 + c) * D_DIM + k0 + q * 8;
                cp_async16(smA + STAGE_A_BYTES + br * ROWB + q * 16, gb);
            }
        }
        asm volatile("cp.async.commit_group;");
    };

    float acc[2][8][4] = {};          // [mi][ni][regs] : 32x64 warp tile
    uint32_t af[2][4];                // single-buffered (4 warps/SMSP hide lat)
    uint32_t bf[4][4];

    load_stage(0, 0);
    load_stage(1, BK);

    for (int it = 0; it < NITER; it++) {
        asm volatile("cp.async.wait_group %0;" :: "n"(STAGES - 2));
        __syncthreads();
        const int cs = it % STAGES;
        const uint32_t sA = sbase + (uint32_t)cs * STAGE_BYTES;
        const uint32_t sB = sA + STAGE_A_BYTES;

        if (it + STAGES - 1 < NITER)
            load_stage((it + STAGES - 1) % STAGES, (it + STAGES - 1) * BK);

        #pragma unroll
        for (int kk = 0; kk < 4; kk++) {          // 4 x k16 per stage
            const uint32_t ko = (uint32_t)kk * 32u;
            #pragma unroll
            for (int mi = 0; mi < 2; mi++)
                ldsm_x4(af[mi], sA + aoff + (uint32_t)mi * (16u * ROWB) + ko);
            #pragma unroll
            for (int nb = 0; nb < 4; nb++)
                ldsm_x4(bf[nb], sB + boff + (uint32_t)nb * (16u * ROWB) + ko);
            #pragma unroll
            for (int mi = 0; mi < 2; mi++)
                #pragma unroll
                for (int nb = 0; nb < 4; nb++) {
                    mma_f16(acc[mi][2 * nb],     af[mi], &bf[nb][0]);
                    mma_f16(acc[mi][2 * nb + 1], af[mi], &bf[nb][2]);
                }
        }
    }

    // ---- stage accumulators through smem: thread gathers (p,th,re,im) ----
    asm volatile("cp.async.wait_group 0;");
    __syncthreads();
    float* epi = sm;   // 128 x EPI_STRIDE (133 KB <= SMEM_MAIN)
    #pragma unroll
    for (int mi = 0; mi < 2; mi++)
        #pragma unroll
        for (int ni = 0; ni < 8; ni++) {
            const int r = wm + mi * 16 + g;
            const int n = wn + ni * 8 + 2 * tg;
            epi[r * EPI_STRIDE + n]           = acc[mi][ni][0];
            epi[r * EPI_STRIDE + n + 1]       = acc[mi][ni][1];
            epi[(r + 8) * EPI_STRIDE + n]     = acc[mi][ni][2];
            epi[(r + 8) * EPI_STRIDE + n + 1] = acc[mi][ni][3];
        }
    __syncthreads();

    // ---- fused epilogue: sigmoid gate + rotation + blend ----
    const int rowt = tid >> 4;            // 0..31
    const int cb = (tid & 15) * 4;        // 0..60
    const int ng = nt * 64 + cb;
    const float4 bp = *(const float4*)&b_p[ng];
    const float4 bt = *(const float4*)&b_th[ng];
    const float4 br = *(const float4*)&b_r[ng];
    const float4 bi = *(const float4*)&b_i[ng];

    #pragma unroll
    for (int rep = 0; rep < 4; rep++) {
        const int m = rep * 32 + rowt;
        const size_t gm = (size_t)(mt * 128 + m);
        const float4 pl = *(const float4*)&epi[m * EPI_STRIDE + 0 * 64 + cb];
        const float4 th = *(const float4*)&epi[m * EPI_STRIDE + 1 * 64 + cb];
        const float4 xr = *(const float4*)&epi[m * EPI_STRIDE + 2 * 64 + cb];
        const float4 xi = *(const float4*)&epi[m * EPI_STRIDE + 3 * 64 + cb];
        const float4 hr = *(const float4*)&h_prev[gm * (2 * D_DIM) + ng];
        const float4 hi = *(const float4*)&h_prev[gm * (2 * D_DIM) + D_DIM + ng];

        float plv[4] = {pl.x + bp.x, pl.y + bp.y, pl.z + bp.z, pl.w + bp.w};
        float thv[4] = {th.x + bt.x, th.y + bt.y, th.z + bt.z, th.w + bt.w};
        float xrv[4] = {xr.x + br.x, xr.y + br.y, xr.z + br.z, xr.w + br.w};
        float xiv[4] = {xi.x + bi.x, xi.y + bi.y, xi.z + bi.z, xi.w + bi.w};
        float hrv[4] = {hr.x, hr.y, hr.z, hr.w};
        float hiv[4] = {hi.x, hi.y, hi.z, hi.w};
        float ore[4], oim[4];
        #pragma unroll
        for (int c = 0; c < 4; c++) {
            const float p = 1.0f / (1.0f + __expf(-plv[c]));
            float sn, cs;
            __sincosf(thv[c], &sn, &cs);
            const float rre = cs * hrv[c] - sn * hiv[c];
            const float rim = sn * hrv[c] + cs * hiv[c];
            ore[c] = rre + p * (xrv[c] - rre);
            oim[c] = rim + p * (xiv[c] - rim);
        }
        *(float4*)&out[gm * (2 * D_DIM) + ng] =
            make_float4(ore[0], ore[1], ore[2], ore[3]);
        *(float4*)&out[gm * (2 * D_DIM) + D_DIM + ng] =
            make_float4(oim[0], oim[1], oim[2], oim[3]);
    }
}

// ---------------------------------------------------------------------------
// Host
// ---------------------------------------------------------------------------
extern "C" void kernel_launch(void* const* d_in, const int* in_sizes, int n_in,
                              void* d_out, int out_size) {
    const float* e_t    = (const float*)d_in[0];
    const float* h_prev = (const float*)d_in[1];
    const float* W_p    = (const float*)d_in[2];
    const float* b_p    = (const float*)d_in[3];
    const float* W_th   = (const float*)d_in[4];
    const float* b_th   = (const float*)d_in[5];
    const float* W_r    = (const float*)d_in[6];
    const float* b_r    = (const float*)d_in[7];
    const float* W_i    = (const float*)d_in[8];
    const float* b_i    = (const float*)d_in[9];
    float* out = (float*)d_out;

    __half* sA = nullptr; __half* sW = nullptr;
    cudaGetSymbolAddress((void**)&sA, g_Ah);
    cudaGetSymbolAddress((void**)&sW, g_Wh);

    const size_t nA = (size_t)B_DIM * D_DIM;
    const size_t nW = (size_t)D_DIM * D_DIM;
    f2h_kernel<<<2048, 256>>>((const float4*)e_t, (__half2*)sA, (int)(nA / 4));
    f2h4_kernel<<<dim3(512, 4), 256>>>(
        (const float4*)W_p, (const float4*)W_th, (const float4*)W_r,
        (const float4*)W_i, (__half2*)sW, (int)(nW / 4));

    cudaFuncSetAttribute(mipt_kernel, cudaFuncAttributeMaxDynamicSharedMemorySize,
                         SMEM_MAIN);
    // grid: nt-major so a wave shares W tiles; A stays L2-resident
    mipt_kernel<<<64 * 32, NTHREADS, SMEM_MAIN>>>(sA, sW, h_prev,
                                                  b_p, b_th, b_r, b_i, out);
}

// round 12
// speedup vs baseline: 2.2361x; 1.1012x over previous
#include <cuda_runtime.h>
#include <cuda_fp16.h>
#include <cstdint>

// ============================================================================
// MIPT cell, sm_103-portable path (compute_103 virtual arch: no tcgen05).
// fp16 mma.sync m16n8k16 GEMM, CTA 128x128 (32 cols x 4 segments), 8 warps
// (4m x 2n, warp tile 32x64), 2 CTAs/SM for barrier decoupling:
//   proj = e_t @ [W_p; W_th; W_r; W_i]^T + b   (B=8192, D=2048)
// fused with sigmoid / sincos rotation / blend epilogue.
// ============================================================================

#define D_DIM 2048
#define B_DIM 8192
#define BM 128
#define BN 128              // 32 cols x 4 segments
#define BK 64               // K halfs per stage (128B data rows)
#define NITER (D_DIM / BK)  // 32
#define STAGES 3
#define ROWB 144            // padded row bytes (128B data + 16B)
#define STAGE_A_BYTES (BM * ROWB)                // 18432
#define STAGE_B_BYTES (BN * ROWB)                // 18432
#define STAGE_BYTES (STAGE_A_BYTES + STAGE_B_BYTES)  // 36864
#define SMEM_MAIN (STAGES * STAGE_BYTES)         // 110592
#define EPI_STRIDE 132
#define NTHREADS 256

// ---------------------------------------------------------------------------
// Scratch: fp16-rounded operands (__device__ globals; alloc-free rule)
// ---------------------------------------------------------------------------
__device__ __half g_Ah[(size_t)B_DIM * D_DIM];        // 32 MB
__device__ __half g_Wh[(size_t)4 * D_DIM * D_DIM];    // 32 MB

__device__ __forceinline__ uint32_t smem_u32(const void* p) {
    uint32_t a;
    asm("{ .reg .u64 t; cvta.to.shared.u64 t, %1; cvt.u32.u64 %0, t; }" : "=r"(a) : "l"(p));
    return a;
}
__device__ __forceinline__ void cp_async16(uint32_t dst, const void* src) {
    asm volatile("cp.async.cg.shared.global [%0], [%1], 16;" :: "r"(dst), "l"(src));
}
__device__ __forceinline__ void mma_f16(float* d, const uint32_t* a, const uint32_t* b) {
    asm volatile(
        "mma.sync.aligned.m16n8k16.row.col.f32.f16.f16.f32 "
        "{%0,%1,%2,%3}, {%4,%5,%6,%7}, {%8,%9}, {%0,%1,%2,%3};"
        : "+f"(d[0]), "+f"(d[1]), "+f"(d[2]), "+f"(d[3])
        : "r"(a[0]), "r"(a[1]), "r"(a[2]), "r"(a[3]), "r"(b[0]), "r"(b[1]));
}
__device__ __forceinline__ void ldsm_x4(uint32_t* r, uint32_t addr) {
    asm volatile("ldmatrix.sync.aligned.m8n8.x4.shared.b16 {%0,%1,%2,%3}, [%4];"
                 : "=r"(r[0]), "=r"(r[1]), "=r"(r[2]), "=r"(r[3]) : "r"(addr));
}

// ---------------------------------------------------------------------------
// Prepass: fp32 -> fp16 (RN)
// ---------------------------------------------------------------------------
__global__ void f2h_kernel(const float4* __restrict__ src,
                           __half2* __restrict__ dst, int n4) {
    int stride = gridDim.x * blockDim.x;
    for (int i = blockIdx.x * blockDim.x + threadIdx.x; i < n4; i += stride) {
        float4 v = src[i];
        dst[2 * i]     = __floats2half2_rn(v.x, v.y);
        dst[2 * i + 1] = __floats2half2_rn(v.z, v.w);
    }
}
__global__ void f2h4_kernel(const float4* __restrict__ s0,
                            const float4* __restrict__ s1,
                            const float4* __restrict__ s2,
                            const float4* __restrict__ s3,
                            __half2* __restrict__ dst, int n4) {
    const float4* src = (blockIdx.y == 0) ? s0 : (blockIdx.y == 1) ? s1
                       : (blockIdx.y == 2) ? s2 : s3;
    __half2* d = dst + (size_t)blockIdx.y * n4 * 2;
    int stride = gridDim.x * blockDim.x;
    for (int i = blockIdx.x * blockDim.x + threadIdx.x; i < n4; i += stride) {
        float4 v = src[i];
        d[2 * i]     = __floats2half2_rn(v.x, v.y);
        d[2 * i + 1] = __floats2half2_rn(v.z, v.w);
    }
}

// ---------------------------------------------------------------------------
// Fused GEMM + epilogue
// ---------------------------------------------------------------------------
__global__ void __launch_bounds__(NTHREADS, 2)
mipt_kernel(const __half* __restrict__ gA, const __half* __restrict__ gW,
            const float* __restrict__ h_prev,
            const float* __restrict__ b_p, const float* __restrict__ b_th,
            const float* __restrict__ b_r, const float* __restrict__ b_i,
            float* __restrict__ out) {
    extern __shared__ float sm[];
    const int tid = threadIdx.x;
    const int bx = blockIdx.x;
    const int mt = bx & 63;          // m-tile (64)
    const int nt = bx >> 6;          // n-tile (64; 32 cols per segment)
    const uint32_t sbase = smem_u32(sm);

    const int wid = tid >> 5, lane = tid & 31;
    const int g = lane >> 2, tg = lane & 3;
    const int wm = (wid & 3) * 32;   // warp m offset (4 m-warps)
    const int wn = (wid >> 2) * 64;  // warp n offset (2 n-warps)

    // ldmatrix per-lane base byte offsets (within a stage)
    const uint32_t aoff =
        (uint32_t)((wm + (lane & 15)) * ROWB) + ((uint32_t)(lane >> 4) << 4);
    const int rowB = wn + (lane & 7) + ((lane >> 4) << 3);
    const uint32_t boff =
        (uint32_t)(rowB * ROWB) + (((uint32_t)(lane >> 3) & 1u) << 4);

    // ---- async stage loader: A [128 x 64h] + B [128 x 64h] = 2048 chunks ----
    auto load_stage = [&](int s, int k0) {
        const uint32_t smA = sbase + s * STAGE_BYTES;
        #pragma unroll
        for (int r = 0; r < 8; r++) {
            const int ch = tid + r * NTHREADS;    // 0..2047
            const int row = ch >> 3, q = ch & 7;  // 8 x 16B chunks (8 halfs each)
            if (row < BM) {
                const __half* ga = gA + (size_t)(mt * 128 + row) * D_DIM + k0 + q * 8;
                cp_async16(smA + row * ROWB + q * 16, ga);
            } else {
                const int br = row - BM;          // 0..127
                const int j = br >> 5, c = br & 31;
                const __half* gb = gW + (size_t)j * (D_DIM * D_DIM)
                                      + (size_t)(nt * 32 + c) * D_DIM + k0 + q * 8;
                cp_async16(smA + STAGE_A_BYTES + br * ROWB + q * 16, gb);
            }
        }
        asm volatile("cp.async.commit_group;");
    };

    float acc[2][8][4] = {};          // [mi][ni][regs] : 32x64 warp tile
    uint32_t af[2][4];                // single-buffered fragments
    uint32_t bf[4][4];

    load_stage(0, 0);
    load_stage(1, BK);

    for (int it = 0; it < NITER; it++) {
        asm volatile("cp.async.wait_group %0;" :: "n"(STAGES - 2));
        __syncthreads();
        const int cs = it % STAGES;
        const uint32_t sA = sbase + (uint32_t)cs * STAGE_BYTES;
        const uint32_t sB = sA + STAGE_A_BYTES;

        if (it + STAGES - 1 < NITER)
            load_stage((it + STAGES - 1) % STAGES, (it + STAGES - 1) * BK);

        #pragma unroll
        for (int kk = 0; kk < 4; kk++) {          // 4 x k16 per stage
            const uint32_t ko = (uint32_t)kk * 32u;
            #pragma unroll
            for (int mi = 0; mi < 2; mi++)
                ldsm_x4(af[mi], sA + aoff + (uint32_t)mi * (16u * ROWB) + ko);
            #pragma unroll
            for (int nb = 0; nb < 4; nb++)
                ldsm_x4(bf[nb], sB + boff + (uint32_t)nb * (16u * ROWB) + ko);
            #pragma unroll
            for (int mi = 0; mi < 2; mi++)
                #pragma unroll
                for (int nb = 0; nb < 4; nb++) {
                    mma_f16(acc[mi][2 * nb],     af[mi], &bf[nb][0]);
                    mma_f16(acc[mi][2 * nb + 1], af[mi], &bf[nb][2]);
                }
        }
    }

    // ---- stage accumulators through smem: thread gathers (p,th,re,im) ----
    asm volatile("cp.async.wait_group 0;");
    __syncthreads();
    float* epi = sm;   // 128 x EPI_STRIDE (67.6 KB <= SMEM_MAIN)
    #pragma unroll
    for (int mi = 0; mi < 2; mi++)
        #pragma unroll
        for (int ni = 0; ni < 8; ni++) {
            const int r = wm + mi * 16 + g;
            const int n = wn + ni * 8 + 2 * tg;
            epi[r * EPI_STRIDE + n]           = acc[mi][ni][0];
            epi[r * EPI_STRIDE + n + 1]       = acc[mi][ni][1];
            epi[(r + 8) * EPI_STRIDE + n]     = acc[mi][ni][2];
            epi[(r + 8) * EPI_STRIDE + n + 1] = acc[mi][ni][3];
        }
    __syncthreads();

    // ---- fused epilogue: sigmoid gate + rotation + blend ----
    const int rowt = tid >> 3;            // 0..31
    const int cb = (tid & 7) * 4;         // 0..28
    const int ng = nt * 32 + cb;
    const float4 bp = *(const float4*)&b_p[ng];
    const float4 bt = *(const float4*)&b_th[ng];
    const float4 br = *(const float4*)&b_r[ng];
    const float4 bi = *(const float4*)&b_i[ng];

    #pragma unroll
    for (int rep = 0; rep < 4; rep++) {
        const int m = rep * 32 + rowt;
        const size_t gm = (size_t)(mt * 128 + m);
        const float4 pl = *(const float4*)&epi[m * EPI_STRIDE + 0 * 32 + cb];
        const float4 th = *(const float4*)&epi[m * EPI_STRIDE + 1 * 32 + cb];
        const float4 xr = *(const float4*)&epi[m * EPI_STRIDE + 2 * 32 + cb];
        const float4 xi = *(const float4*)&epi[m * EPI_STRIDE + 3 * 32 + cb];
        const float4 hr = *(const float4*)&h_prev[gm * (2 * D_DIM) + ng];
        const float4 hi = *(const float4*)&h_prev[gm * (2 * D_DIM) + D_DIM + ng];

        float plv[4] = {pl.x + bp.x, pl.y + bp.y, pl.z + bp.z, pl.w + bp.w};
        float thv[4] = {th.x + bt.x, th.y + bt.y, th.z + bt.z, th.w + bt.w};
        float xrv[4] = {xr.x + br.x, xr.y + br.y, xr.z + br.z, xr.w + br.w};
        float xiv[4] = {xi.x + bi.x, xi.y + bi.y, xi.z + bi.z, xi.w + bi.w};
        float hrv[4] = {hr.x, hr.y, hr.z, hr.w};
        float hiv[4] = {hi.x, hi.y, hi.z, hi.w};
        float ore[4], oim[4];
        #pragma unroll
        for (int c = 0; c < 4; c++) {
            const float p = 1.0f / (1.0f + __expf(-plv[c]));
            float sn, cs;
            __sincosf(thv[c], &sn, &cs);
            const float rre = cs * hrv[c] - sn * hiv[c];
            const float rim = sn * hrv[c] + cs * hiv[c];
            ore[c] = rre + p * (xrv[c] - rre);
            oim[c] = rim + p * (xiv[c] - rim);
        }
        *(float4*)&out[gm * (2 * D_DIM) + ng] =
            make_float4(ore[0], ore[1], ore[2], ore[3]);
        *(float4*)&out[gm * (2 * D_DIM) + D_DIM + ng] =
            make_float4(oim[0], oim[1], oim[2], oim[3]);
    }
}

// ---------------------------------------------------------------------------
// Host
// ---------------------------------------------------------------------------
extern "C" void kernel_launch(void* const* d_in, const int* in_sizes, int n_in,
                              void* d_out, int out_size) {
    const float* e_t    = (const float*)d_in[0];
    const float* h_prev = (const float*)d_in[1];
    const float* W_p    = (const float*)d_in[2];
    const float* b_p    = (const float*)d_in[3];
    const float* W_th   = (const float*)d_in[4];
    const float* b_th   = (const float*)d_in[5];
    const float* W_r    = (const float*)d_in[6];
    const float* b_r    = (const float*)d_in[7];
    const float* W_i    = (const float*)d_in[8];
    const float* b_i    = (const float*)d_in[9];
    float* out = (float*)d_out;

    __half* sA = nullptr; __half* sW = nullptr;
    cudaGetSymbolAddress((void**)&sA, g_Ah);
    cudaGetSymbolAddress((void**)&sW, g_Wh);

    const size_t nA = (size_t)B_DIM * D_DIM;
    const size_t nW = (size_t)D_DIM * D_DIM;
    f2h_kernel<<<2048, 256>>>((const float4*)e_t, (__half2*)sA, (int)(nA / 4));
    f2h4_kernel<<<dim3(512, 4), 256>>>(
        (const float4*)W_p, (const float4*)W_th, (const float4*)W_r,
        (const float4*)W_i, (__half2*)sW, (int)(nW / 4));

    cudaFuncSetAttribute(mipt_kernel, cudaFuncAttributeMaxDynamicSharedMemorySize,
                         SMEM_MAIN);
    // grid: nt-major so a wave shares W tiles; A stays L2-resident
    mipt_kernel<<<64 * 64, NTHREADS, SMEM_MAIN>>>(sA, sW, h_prev,
                                                  b_p, b_th, b_r, b_i, out);
}

// round 13
// speedup vs baseline: 2.2788x; 1.0191x over previous
#include <cuda_runtime.h>
#include <cuda_fp16.h>
#include <cstdint>

// ============================================================================
// MIPT cell, sm_103-portable path (compute_103 virtual arch: no tcgen05).
// fp16 mma.sync m16n8k16 GEMM, CTA 128x128 (32 cols x 4 segments), 8 warps
// (4m x 2n, warp tile 32x64), 2 CTAs/SM for barrier decoupling, plus
// register double-buffered fragments across k-steps:
//   proj = e_t @ [W_p; W_th; W_r; W_i]^T + b   (B=8192, D=2048)
// fused with sigmoid / sincos rotation / blend epilogue.
// ============================================================================

#define D_DIM 2048
#define B_DIM 8192
#define BM 128
#define BN 128              // 32 cols x 4 segments
#define BK 64               // K halfs per stage (128B data rows)
#define NITER (D_DIM / BK)  // 32
#define STAGES 3
#define ROWB 144            // padded row bytes (128B data + 16B)
#define STAGE_A_BYTES (BM * ROWB)                // 18432
#define STAGE_B_BYTES (BN * ROWB)                // 18432
#define STAGE_BYTES (STAGE_A_BYTES + STAGE_B_BYTES)  // 36864
#define SMEM_MAIN (STAGES * STAGE_BYTES)         // 110592
#define EPI_STRIDE 132
#define NTHREADS 256

// ---------------------------------------------------------------------------
// Scratch: fp16-rounded operands (__device__ globals; alloc-free rule)
// ---------------------------------------------------------------------------
__device__ __half g_Ah[(size_t)B_DIM * D_DIM];        // 32 MB
__device__ __half g_Wh[(size_t)4 * D_DIM * D_DIM];    // 32 MB

__device__ __forceinline__ uint32_t smem_u32(const void* p) {
    uint32_t a;
    asm("{ .reg .u64 t; cvta.to.shared.u64 t, %1; cvt.u32.u64 %0, t; }" : "=r"(a) : "l"(p));
    return a;
}
__device__ __forceinline__ void cp_async16(uint32_t dst, const void* src) {
    asm volatile("cp.async.cg.shared.global [%0], [%1], 16;" :: "r"(dst), "l"(src));
}
__device__ __forceinline__ void mma_f16(float* d, const uint32_t* a, const uint32_t* b) {
    asm volatile(
        "mma.sync.aligned.m16n8k16.row.col.f32.f16.f16.f32 "
        "{%0,%1,%2,%3}, {%4,%5,%6,%7}, {%8,%9}, {%0,%1,%2,%3};"
        : "+f"(d[0]), "+f"(d[1]), "+f"(d[2]), "+f"(d[3])
        : "r"(a[0]), "r"(a[1]), "r"(a[2]), "r"(a[3]), "r"(b[0]), "r"(b[1]));
}
__device__ __forceinline__ void ldsm_x4(uint32_t* r, uint32_t addr) {
    asm volatile("ldmatrix.sync.aligned.m8n8.x4.shared.b16 {%0,%1,%2,%3}, [%4];"
                 : "=r"(r[0]), "=r"(r[1]), "=r"(r[2]), "=r"(r[3]) : "r"(addr));
}

// ---------------------------------------------------------------------------
// Prepass: fp32 -> fp16 (RN)
// ---------------------------------------------------------------------------
__global__ void f2h_kernel(const float4* __restrict__ src,
                           __half2* __restrict__ dst, int n4) {
    int stride = gridDim.x * blockDim.x;
    for (int i = blockIdx.x * blockDim.x + threadIdx.x; i < n4; i += stride) {
        float4 v = src[i];
        dst[2 * i]     = __floats2half2_rn(v.x, v.y);
        dst[2 * i + 1] = __floats2half2_rn(v.z, v.w);
    }
}
__global__ void f2h4_kernel(const float4* __restrict__ s0,
                            const float4* __restrict__ s1,
                            const float4* __restrict__ s2,
                            const float4* __restrict__ s3,
                            __half2* __restrict__ dst, int n4) {
    const float4* src = (blockIdx.y == 0) ? s0 : (blockIdx.y == 1) ? s1
                       : (blockIdx.y == 2) ? s2 : s3;
    __half2* d = dst + (size_t)blockIdx.y * n4 * 2;
    int stride = gridDim.x * blockDim.x;
    for (int i = blockIdx.x * blockDim.x + threadIdx.x; i < n4; i += stride) {
        float4 v = src[i];
        d[2 * i]     = __floats2half2_rn(v.x, v.y);
        d[2 * i + 1] = __floats2half2_rn(v.z, v.w);
    }
}

// ---------------------------------------------------------------------------
// Fused GEMM + epilogue
// ---------------------------------------------------------------------------
__global__ void __launch_bounds__(NTHREADS, 2)
mipt_kernel(const __half* __restrict__ gA, const __half* __restrict__ gW,
            const float* __restrict__ h_prev,
            const float* __restrict__ b_p, const float* __restrict__ b_th,
            const float* __restrict__ b_r, const float* __restrict__ b_i,
            float* __restrict__ out) {
    extern __shared__ float sm[];
    const int tid = threadIdx.x;
    const int bx = blockIdx.x;
    const int mt = bx & 63;          // m-tile (64)
    const int nt = bx >> 6;          // n-tile (64; 32 cols per segment)
    const uint32_t sbase = smem_u32(sm);

    const int wid = tid >> 5, lane = tid & 31;
    const int g = lane >> 2, tg = lane & 3;
    const int wm = (wid & 3) * 32;   // warp m offset (4 m-warps)
    const int wn = (wid >> 2) * 64;  // warp n offset (2 n-warps)

    // ldmatrix per-lane base byte offsets (within a stage)
    const uint32_t aoff =
        (uint32_t)((wm + (lane & 15)) * ROWB) + ((uint32_t)(lane >> 4) << 4);
    const int rowB = wn + (lane & 7) + ((lane >> 4) << 3);
    const uint32_t boff =
        (uint32_t)(rowB * ROWB) + (((uint32_t)(lane >> 3) & 1u) << 4);

    // ---- async stage loader: A [128 x 64h] + B [128 x 64h] = 2048 chunks ----
    auto load_stage = [&](int s, int k0) {
        const uint32_t smA = sbase + s * STAGE_BYTES;
        #pragma unroll
        for (int r = 0; r < 8; r++) {
            const int ch = tid + r * NTHREADS;    // 0..2047
            const int row = ch >> 3, q = ch & 7;  // 8 x 16B chunks (8 halfs each)
            if (row < BM) {
                const __half* ga = gA + (size_t)(mt * 128 + row) * D_DIM + k0 + q * 8;
                cp_async16(smA + row * ROWB + q * 16, ga);
            } else {
                const int br = row - BM;          // 0..127
                const int j = br >> 5, c = br & 31;
                const __half* gb = gW + (size_t)j * (D_DIM * D_DIM)
                                      + (size_t)(nt * 32 + c) * D_DIM + k0 + q * 8;
                cp_async16(smA + STAGE_A_BYTES + br * ROWB + q * 16, gb);
            }
        }
        asm volatile("cp.async.commit_group;");
    };

    float acc[2][8][4] = {};          // [mi][ni][regs] : 32x64 warp tile
    uint32_t af[2][2][4];             // [buf][mi][regs] (double-buffered)
    uint32_t bf[2][4][4];             // [buf][nb][regs]

    load_stage(0, 0);
    load_stage(1, BK);

    for (int it = 0; it < NITER; it++) {
        asm volatile("cp.async.wait_group %0;" :: "n"(STAGES - 2));
        __syncthreads();
        const int cs = it % STAGES;
        const uint32_t sA = sbase + (uint32_t)cs * STAGE_BYTES;
        const uint32_t sB = sA + STAGE_A_BYTES;

        // prefetch kk=0 fragments before the cp.async issue burst
        #pragma unroll
        for (int mi = 0; mi < 2; mi++)
            ldsm_x4(af[0][mi], sA + aoff + (uint32_t)mi * (16u * ROWB));
        #pragma unroll
        for (int nb = 0; nb < 4; nb++)
            ldsm_x4(bf[0][nb], sB + boff + (uint32_t)nb * (16u * ROWB));

        if (it + STAGES - 1 < NITER)
            load_stage((it + STAGES - 1) % STAGES, (it + STAGES - 1) * BK);

        #pragma unroll
        for (int kk = 0; kk < 4; kk++) {          // 4 x k16 per stage
            const int cur = kk & 1, nxt = cur ^ 1;
            if (kk < 3) {   // prefetch kk+1 fragments (+32B per k16 step)
                const uint32_t ko = (uint32_t)(kk + 1) * 32u;
                #pragma unroll
                for (int mi = 0; mi < 2; mi++)
                    ldsm_x4(af[nxt][mi],
                            sA + aoff + (uint32_t)mi * (16u * ROWB) + ko);
                #pragma unroll
                for (int nb = 0; nb < 4; nb++)
                    ldsm_x4(bf[nxt][nb],
                            sB + boff + (uint32_t)nb * (16u * ROWB) + ko);
            }
            #pragma unroll
            for (int mi = 0; mi < 2; mi++)
                #pragma unroll
                for (int nb = 0; nb < 4; nb++) {
                    mma_f16(acc[mi][2 * nb],     af[cur][mi], &bf[cur][nb][0]);
                    mma_f16(acc[mi][2 * nb + 1], af[cur][mi], &bf[cur][nb][2]);
                }
        }
    }

    // ---- stage accumulators through smem: thread gathers (p,th,re,im) ----
    asm volatile("cp.async.wait_group 0;");
    __syncthreads();
    float* epi = sm;   // 128 x EPI_STRIDE (67.6 KB <= SMEM_MAIN)
    #pragma unroll
    for (int mi = 0; mi < 2; mi++)
        #pragma unroll
        for (int ni = 0; ni < 8; ni++) {
            const int r = wm + mi * 16 + g;
            const int n = wn + ni * 8 + 2 * tg;
            epi[r * EPI_STRIDE + n]           = acc[mi][ni][0];
            epi[r * EPI_STRIDE + n + 1]       = acc[mi][ni][1];
            epi[(r + 8) * EPI_STRIDE + n]     = acc[mi][ni][2];
            epi[(r + 8) * EPI_STRIDE + n + 1] = acc[mi][ni][3];
        }
    __syncthreads();

    // ---- fused epilogue: sigmoid gate + rotation + blend ----
    const int rowt = tid >> 3;            // 0..31
    const int cb = (tid & 7) * 4;         // 0..28
    const int ng = nt * 32 + cb;
    const float4 bp = *(const float4*)&b_p[ng];
    const float4 bt = *(const float4*)&b_th[ng];
    const float4 br = *(const float4*)&b_r[ng];
    const float4 bi = *(const float4*)&b_i[ng];

    #pragma unroll
    for (int rep = 0; rep < 4; rep++) {
        const int m = rep * 32 + rowt;
        const size_t gm = (size_t)(mt * 128 + m);
        const float4 pl = *(const float4*)&epi[m * EPI_STRIDE + 0 * 32 + cb];
        const float4 th = *(const float4*)&epi[m * EPI_STRIDE + 1 * 32 + cb];
        const float4 xr = *(const float4*)&epi[m * EPI_STRIDE + 2 * 32 + cb];
        const float4 xi = *(const float4*)&epi[m * EPI_STRIDE + 3 * 32 + cb];
        const float4 hr = *(const float4*)&h_prev[gm * (2 * D_DIM) + ng];
        const float4 hi = *(const float4*)&h_prev[gm * (2 * D_DIM) + D_DIM + ng];

        float plv[4] = {pl.x + bp.x, pl.y + bp.y, pl.z + bp.z, pl.w + bp.w};
        float thv[4] = {th.x + bt.x, th.y + bt.y, th.z + bt.z, th.w + bt.w};
        float xrv[4] = {xr.x + br.x, xr.y + br.y, xr.z + br.z, xr.w + br.w};
        float xiv[4] = {xi.x + bi.x, xi.y + bi.y, xi.z + bi.z, xi.w + bi.w};
        float hrv[4] = {hr.x, hr.y, hr.z, hr.w};
        float hiv[4] = {hi.x, hi.y, hi.z, hi.w};
        float ore[4], oim[4];
        #pragma unroll
        for (int c = 0; c < 4; c++) {
            const float p = 1.0f / (1.0f + __expf(-plv[c]));
            float sn, cs;
            __sincosf(thv[c], &sn, &cs);
            const float rre = cs * hrv[c] - sn * hiv[c];
            const float rim = sn * hrv[c] + cs * hiv[c];
            ore[c] = rre + p * (xrv[c] - rre);
            oim[c] = rim + p * (xiv[c] - rim);
        }
        *(float4*)&out[gm * (2 * D_DIM) + ng] =
            make_float4(ore[0], ore[1], ore[2], ore[3]);
        *(float4*)&out[gm * (2 * D_DIM) + D_DIM + ng] =
            make_float4(oim[0], oim[1], oim[2], oim[3]);
    }
}

// ---------------------------------------------------------------------------
// Host
// ---------------------------------------------------------------------------
extern "C" void kernel_launch(void* const* d_in, const int* in_sizes, int n_in,
                              void* d_out, int out_size) {
    const float* e_t    = (const float*)d_in[0];
    const float* h_prev = (const float*)d_in[1];
    const float* W_p    = (const float*)d_in[2];
    const float* b_p    = (const float*)d_in[3];
    const float* W_th   = (const float*)d_in[4];
    const float* b_th   = (const float*)d_in[5];
    const float* W_r    = (const float*)d_in[6];
    const float* b_r    = (const float*)d_in[7];
    const float* W_i    = (const float*)d_in[8];
    const float* b_i    = (const float*)d_in[9];
    float* out = (float*)d_out;

    __half* sA = nullptr; __half* sW = nullptr;
    cudaGetSymbolAddress((void**)&sA, g_Ah);
    cudaGetSymbolAddress((void**)&sW, g_Wh);

    const size_t nA = (size_t)B_DIM * D_DIM;
    const size_t nW = (size_t)D_DIM * D_DIM;
    f2h_kernel<<<2048, 256>>>((const float4*)e_t, (__half2*)sA, (int)(nA / 4));
    f2h4_kernel<<<dim3(512, 4), 256>>>(
        (const float4*)W_p, (const float4*)W_th, (const float4*)W_r,
        (const float4*)W_i, (__half2*)sW, (int)(nW / 4));

    cudaFuncSetAttribute(mipt_kernel, cudaFuncAttributeMaxDynamicSharedMemorySize,
                         SMEM_MAIN);
    // grid: nt-major so a wave shares W tiles; A stays L2-resident
    mipt_kernel<<<64 * 64, NTHREADS, SMEM_MAIN>>>(sA, sW, h_prev,
                                                  b_p, b_th, b_r, b_i, out);
}

// round 14
// speedup vs baseline: 2.3177x; 1.0171x over previous
#include <cuda_runtime.h>
#include <cuda_fp16.h>
#include <cstdint>

// ============================================================================
// MIPT cell, sm_103-portable path (compute_103 virtual arch: no tcgen05).
// fp16 mma.sync m16n8k16 GEMM, CTA 128x128 (32 cols x 4 segments), 8 warps
// (4m x 2n, warp tile 32x64), 2 CTAs/SM, double-buffered fragments, plus
// L2 prefetch of the epilogue's h_prev slice during the mainloop:
//   proj = e_t @ [W_p; W_th; W_r; W_i]^T + b   (B=8192, D=2048)
// fused with sigmoid / sincos rotation / blend epilogue.
// ============================================================================

#define D_DIM 2048
#define B_DIM 8192
#define BM 128
#define BN 128              // 32 cols x 4 segments
#define BK 64               // K halfs per stage (128B data rows)
#define NITER (D_DIM / BK)  // 32
#define STAGES 3
#define ROWB 144            // padded row bytes (128B data + 16B)
#define STAGE_A_BYTES (BM * ROWB)                // 18432
#define STAGE_B_BYTES (BN * ROWB)                // 18432
#define STAGE_BYTES (STAGE_A_BYTES + STAGE_B_BYTES)  // 36864
#define SMEM_MAIN (STAGES * STAGE_BYTES)         // 110592
#define EPI_STRIDE 132
#define NTHREADS 256

// ---------------------------------------------------------------------------
// Scratch: fp16-rounded operands (__device__ globals; alloc-free rule)
// ---------------------------------------------------------------------------
__device__ __half g_Ah[(size_t)B_DIM * D_DIM];        // 32 MB
__device__ __half g_Wh[(size_t)4 * D_DIM * D_DIM];    // 32 MB

__device__ __forceinline__ uint32_t smem_u32(const void* p) {
    uint32_t a;
    asm("{ .reg .u64 t; cvta.to.shared.u64 t, %1; cvt.u32.u64 %0, t; }" : "=r"(a) : "l"(p));
    return a;
}
__device__ __forceinline__ void cp_async16(uint32_t dst, const void* src) {
    asm volatile("cp.async.cg.shared.global [%0], [%1], 16;" :: "r"(dst), "l"(src));
}
__device__ __forceinline__ void prefetch_l2(const void* p) {
    asm volatile("prefetch.global.L2 [%0];" :: "l"(p));
}
__device__ __forceinline__ void mma_f16(float* d, const uint32_t* a, const uint32_t* b) {
    asm volatile(
        "mma.sync.aligned.m16n8k16.row.col.f32.f16.f16.f32 "
        "{%0,%1,%2,%3}, {%4,%5,%6,%7}, {%8,%9}, {%0,%1,%2,%3};"
        : "+f"(d[0]), "+f"(d[1]), "+f"(d[2]), "+f"(d[3])
        : "r"(a[0]), "r"(a[1]), "r"(a[2]), "r"(a[3]), "r"(b[0]), "r"(b[1]));
}
__device__ __forceinline__ void ldsm_x4(uint32_t* r, uint32_t addr) {
    asm volatile("ldmatrix.sync.aligned.m8n8.x4.shared.b16 {%0,%1,%2,%3}, [%4];"
                 : "=r"(r[0]), "=r"(r[1]), "=r"(r[2]), "=r"(r[3]) : "r"(addr));
}

// ---------------------------------------------------------------------------
// Prepass: fp32 -> fp16 (RN)
// ---------------------------------------------------------------------------
__global__ void f2h_kernel(const float4* __restrict__ src,
                           __half2* __restrict__ dst, int n4) {
    int stride = gridDim.x * blockDim.x;
    for (int i = blockIdx.x * blockDim.x + threadIdx.x; i < n4; i += stride) {
        float4 v = src[i];
        dst[2 * i]     = __floats2half2_rn(v.x, v.y);
        dst[2 * i + 1] = __floats2half2_rn(v.z, v.w);
    }
}
__global__ void f2h4_kernel(const float4* __restrict__ s0,
                            const float4* __restrict__ s1,
                            const float4* __restrict__ s2,
                            const float4* __restrict__ s3,
                            __half2* __restrict__ dst, int n4) {
    const float4* src = (blockIdx.y == 0) ? s0 : (blockIdx.y == 1) ? s1
                       : (blockIdx.y == 2) ? s2 : s3;
    __half2* d = dst + (size_t)blockIdx.y * n4 * 2;
    int stride = gridDim.x * blockDim.x;
    for (int i = blockIdx.x * blockDim.x + threadIdx.x; i < n4; i += stride) {
        float4 v = src[i];
        d[2 * i]     = __floats2half2_rn(v.x, v.y);
        d[2 * i + 1] = __floats2half2_rn(v.z, v.w);
    }
}

// ---------------------------------------------------------------------------
// Fused GEMM + epilogue
// ---------------------------------------------------------------------------
__global__ void __launch_bounds__(NTHREADS, 2)
mipt_kernel(const __half* __restrict__ gA, const __half* __restrict__ gW,
            const float* __restrict__ h_prev,
            const float* __restrict__ b_p, const float* __restrict__ b_th,
            const float* __restrict__ b_r, const float* __restrict__ b_i,
            float* __restrict__ out) {
    extern __shared__ float sm[];
    const int tid = threadIdx.x;
    const int bx = blockIdx.x;
    const int mt = bx & 63;          // m-tile (64)
    const int nt = bx >> 6;          // n-tile (64; 32 cols per segment)
    const uint32_t sbase = smem_u32(sm);

    const int wid = tid >> 5, lane = tid & 31;
    const int g = lane >> 2, tg = lane & 3;
    const int wm = (wid & 3) * 32;   // warp m offset (4 m-warps)
    const int wn = (wid >> 2) * 64;  // warp n offset (2 n-warps)

    // ldmatrix per-lane base byte offsets (within a stage)
    const uint32_t aoff =
        (uint32_t)((wm + (lane & 15)) * ROWB) + ((uint32_t)(lane >> 4) << 4);
    const int rowB = wn + (lane & 7) + ((lane >> 4) << 3);
    const uint32_t boff =
        (uint32_t)(rowB * ROWB) + (((uint32_t)(lane >> 3) & 1u) << 4);

    // ---- async stage loader: A [128 x 64h] + B [128 x 64h] = 2048 chunks ----
    auto load_stage = [&](int s, int k0) {
        const uint32_t smA = sbase + s * STAGE_BYTES;
        #pragma unroll
        for (int r = 0; r < 8; r++) {
            const int ch = tid + r * NTHREADS;    // 0..2047
            const int row = ch >> 3, q = ch & 7;  // 8 x 16B chunks (8 halfs each)
            if (row < BM) {
                const __half* ga = gA + (size_t)(mt * 128 + row) * D_DIM + k0 + q * 8;
                cp_async16(smA + row * ROWB + q * 16, ga);
            } else {
                const int br = row - BM;          // 0..127
                const int j = br >> 5, c = br & 31;
                const __half* gb = gW + (size_t)j * (D_DIM * D_DIM)
                                      + (size_t)(nt * 32 + c) * D_DIM + k0 + q * 8;
                cp_async16(smA + STAGE_A_BYTES + br * ROWB + q * 16, gb);
            }
        }
        asm volatile("cp.async.commit_group;");
    };

    float acc[2][8][4] = {};          // [mi][ni][regs] : 32x64 warp tile
    uint32_t af[2][2][4];             // [buf][mi][regs] (double-buffered)
    uint32_t bf[2][4][4];             // [buf][nb][regs]

    load_stage(0, 0);
    load_stage(1, BK);

    // ---- L2-prefetch this CTA's epilogue inputs (h_prev slice + biases) ----
    // 256 threads x one 128B line = the full 128-row x 32-col (re+im) slice.
    {
        const int prow = tid >> 1;            // 0..127
        const int half = tid & 1;             // 0: re, 1: im
        prefetch_l2(h_prev + (size_t)(mt * 128 + prow) * (2 * D_DIM)
                    + (size_t)half * D_DIM + nt * 32);
        if (tid < 4) {
            const float* bsel = (tid == 0) ? b_p : (tid == 1) ? b_th
                              : (tid == 2) ? b_r : b_i;
            prefetch_l2(bsel + nt * 32);
        }
    }

    for (int it = 0; it < NITER; it++) {
        asm volatile("cp.async.wait_group %0;" :: "n"(STAGES - 2));
        __syncthreads();
        const int cs = it % STAGES;
        const uint32_t sA = sbase + (uint32_t)cs * STAGE_BYTES;
        const uint32_t sB = sA + STAGE_A_BYTES;

        // prefetch kk=0 fragments before the cp.async issue burst
        #pragma unroll
        for (int mi = 0; mi < 2; mi++)
            ldsm_x4(af[0][mi], sA + aoff + (uint32_t)mi * (16u * ROWB));
        #pragma unroll
        for (int nb = 0; nb < 4; nb++)
            ldsm_x4(bf[0][nb], sB + boff + (uint32_t)nb * (16u * ROWB));

        if (it + STAGES - 1 < NITER)
            load_stage((it + STAGES - 1) % STAGES, (it + STAGES - 1) * BK);

        #pragma unroll
        for (int kk = 0; kk < 4; kk++) {          // 4 x k16 per stage
            const int cur = kk & 1, nxt = cur ^ 1;
            if (kk < 3) {   // prefetch kk+1 fragments (+32B per k16 step)
                const uint32_t ko = (uint32_t)(kk + 1) * 32u;
                #pragma unroll
                for (int mi = 0; mi < 2; mi++)
                    ldsm_x4(af[nxt][mi],
                            sA + aoff + (uint32_t)mi * (16u * ROWB) + ko);
                #pragma unroll
                for (int nb = 0; nb < 4; nb++)
                    ldsm_x4(bf[nxt][nb],
                            sB + boff + (uint32_t)nb * (16u * ROWB) + ko);
            }
            #pragma unroll
            for (int mi = 0; mi < 2; mi++)
                #pragma unroll
                for (int nb = 0; nb < 4; nb++) {
                    mma_f16(acc[mi][2 * nb],     af[cur][mi], &bf[cur][nb][0]);
                    mma_f16(acc[mi][2 * nb + 1], af[cur][mi], &bf[cur][nb][2]);
                }
        }
    }

    // ---- stage accumulators through smem: thread gathers (p,th,re,im) ----
    asm volatile("cp.async.wait_group 0;");
    __syncthreads();
    float* epi = sm;   // 128 x EPI_STRIDE (67.6 KB <= SMEM_MAIN)
    #pragma unroll
    for (int mi = 0; mi < 2; mi++)
        #pragma unroll
        for (int ni = 0; ni < 8; ni++) {
            const int r = wm + mi * 16 + g;
            const int n = wn + ni * 8 + 2 * tg;
            epi[r * EPI_STRIDE + n]           = acc[mi][ni][0];
            epi[r * EPI_STRIDE + n + 1]       = acc[mi][ni][1];
            epi[(r + 8) * EPI_STRIDE + n]     = acc[mi][ni][2];
            epi[(r + 8) * EPI_STRIDE + n + 1] = acc[mi][ni][3];
        }
    __syncthreads();

    // ---- fused epilogue: sigmoid gate + rotation + blend ----
    const int rowt = tid >> 3;            // 0..31
    const int cb = (tid & 7) * 4;         // 0..28
    const int ng = nt * 32 + cb;
    const float4 bp = *(const float4*)&b_p[ng];
    const float4 bt = *(const float4*)&b_th[ng];
    const float4 br = *(const float4*)&b_r[ng];
    const float4 bi = *(const float4*)&b_i[ng];

    #pragma unroll
    for (int rep = 0; rep < 4; rep++) {
        const int m = rep * 32 + rowt;
        const size_t gm = (size_t)(mt * 128 + m);
        const float4 pl = *(const float4*)&epi[m * EPI_STRIDE + 0 * 32 + cb];
        const float4 th = *(const float4*)&epi[m * EPI_STRIDE + 1 * 32 + cb];
        const float4 xr = *(const float4*)&epi[m * EPI_STRIDE + 2 * 32 + cb];
        const float4 xi = *(const float4*)&epi[m * EPI_STRIDE + 3 * 32 + cb];
        const float4 hr = *(const float4*)&h_prev[gm * (2 * D_DIM) + ng];
        const float4 hi = *(const float4*)&h_prev[gm * (2 * D_DIM) + D_DIM + ng];

        float plv[4] = {pl.x + bp.x, pl.y + bp.y, pl.z + bp.z, pl.w + bp.w};
        float thv[4] = {th.x + bt.x, th.y + bt.y, th.z + bt.z, th.w + bt.w};
        float xrv[4] = {xr.x + br.x, xr.y + br.y, xr.z + br.z, xr.w + br.w};
        float xiv[4] = {xi.x + bi.x, xi.y + bi.y, xi.z + bi.z, xi.w + bi.w};
        float hrv[4] = {hr.x, hr.y, hr.z, hr.w};
        float hiv[4] = {hi.x, hi.y, hi.z, hi.w};
        float ore[4], oim[4];
        #pragma unroll
        for (int c = 0; c < 4; c++) {
            const float p = 1.0f / (1.0f + __expf(-plv[c]));
            float sn, cs;
            __sincosf(thv[c], &sn, &cs);
            const float rre = cs * hrv[c] - sn * hiv[c];
            const float rim = sn * hrv[c] + cs * hiv[c];
            ore[c] = rre + p * (xrv[c] - rre);
            oim[c] = rim + p * (xiv[c] - rim);
        }
        *(float4*)&out[gm * (2 * D_DIM) + ng] =
            make_float4(ore[0], ore[1], ore[2], ore[3]);
        *(float4*)&out[gm * (2 * D_DIM) + D_DIM + ng] =
            make_float4(oim[0], oim[1], oim[2], oim[3]);
    }
}

// ---------------------------------------------------------------------------
// Host
// ---------------------------------------------------------------------------
extern "C" void kernel_launch(void* const* d_in, const int* in_sizes, int n_in,
                              void* d_out, int out_size) {
    const float* e_t    = (const float*)d_in[0];
    const float* h_prev = (const float*)d_in[1];
    const float* W_p    = (const float*)d_in[2];
    const float* b_p    = (const float*)d_in[3];
    const float* W_th   = (const float*)d_in[4];
    const float* b_th   = (const float*)d_in[5];
    const float* W_r    = (const float*)d_in[6];
    const float* b_r    = (const float*)d_in[7];
    const float* W_i    = (const float*)d_in[8];
    const float* b_i    = (const float*)d_in[9];
    float* out = (float*)d_out;

    __half* sA = nullptr; __half* sW = nullptr;
    cudaGetSymbolAddress((void**)&sA, g_Ah);
    cudaGetSymbolAddress((void**)&sW, g_Wh);

    const size_t nA = (size_t)B_DIM * D_DIM;
    const size_t nW = (size_t)D_DIM * D_DIM;
    f2h_kernel<<<2048, 256>>>((const float4*)e_t, (__half2*)sA, (int)(nA / 4));
    f2h4_kernel<<<dim3(512, 4), 256>>>(
        (const float4*)W_p, (const float4*)W_th, (const float4*)W_r,
        (const float4*)W_i, (__half2*)sW, (int)(nW / 4));

    cudaFuncSetAttribute(mipt_kernel, cudaFuncAttributeMaxDynamicSharedMemorySize,
                         SMEM_MAIN);
    // grid: nt-major so a wave shares W tiles; A stays L2-resident
    mipt_kernel<<<64 * 64, NTHREADS, SMEM_MAIN>>>(sA, sW, h_prev,
                                                  b_p, b_th, b_r, b_i, out);
}

// round 15
// speedup vs baseline: 2.3219x; 1.0018x over previous
#include <cuda_runtime.h>
#include <cuda_fp16.h>
#include <cstdint>

// ============================================================================
// MIPT cell, sm_103-portable path (compute_103 virtual arch: no tcgen05).
// fp16 mma.sync m16n8k16 GEMM, CTA 128x128 (32 cols x 4 segments), 8 warps
// (4m x 2n, warp tile 32x64), 2 CTAs/SM, double-buffered fragments, L2
// prefetch of the epilogue h_prev slice, single merged fp32->fp16 prepass:
//   proj = e_t @ [W_p; W_th; W_r; W_i]^T + b   (B=8192, D=2048)
// fused with sigmoid / sincos rotation / blend epilogue.
// ============================================================================

#define D_DIM 2048
#define B_DIM 8192
#define BM 128
#define BN 128              // 32 cols x 4 segments
#define BK 64               // K halfs per stage (128B data rows)
#define NITER (D_DIM / BK)  // 32
#define STAGES 3
#define ROWB 144            // padded row bytes (128B data + 16B)
#define STAGE_A_BYTES (BM * ROWB)                // 18432
#define STAGE_B_BYTES (BN * ROWB)                // 18432
#define STAGE_BYTES (STAGE_A_BYTES + STAGE_B_BYTES)  // 36864
#define SMEM_MAIN (STAGES * STAGE_BYTES)         // 110592
#define EPI_STRIDE 132
#define NTHREADS 256

// ---------------------------------------------------------------------------
// Scratch: fp16-rounded operands (__device__ globals; alloc-free rule)
// ---------------------------------------------------------------------------
__device__ __half g_Ah[(size_t)B_DIM * D_DIM];        // 32 MB
__device__ __half g_Wh[(size_t)4 * D_DIM * D_DIM];    // 32 MB

__device__ __forceinline__ uint32_t smem_u32(const void* p) {
    uint32_t a;
    asm("{ .reg .u64 t; cvta.to.shared.u64 t, %1; cvt.u32.u64 %0, t; }" : "=r"(a) : "l"(p));
    return a;
}
__device__ __forceinline__ void cp_async16(uint32_t dst, const void* src) {
    asm volatile("cp.async.cg.shared.global [%0], [%1], 16;" :: "r"(dst), "l"(src));
}
__device__ __forceinline__ void prefetch_l2(const void* p) {
    asm volatile("prefetch.global.L2 [%0];" :: "l"(p));
}
__device__ __forceinline__ void mma_f16(float* d, const uint32_t* a, const uint32_t* b) {
    asm volatile(
        "mma.sync.aligned.m16n8k16.row.col.f32.f16.f16.f32 "
        "{%0,%1,%2,%3}, {%4,%5,%6,%7}, {%8,%9}, {%0,%1,%2,%3};"
        : "+f"(d[0]), "+f"(d[1]), "+f"(d[2]), "+f"(d[3])
        : "r"(a[0]), "r"(a[1]), "r"(a[2]), "r"(a[3]), "r"(b[0]), "r"(b[1]));
}
__device__ __forceinline__ void ldsm_x4(uint32_t* r, uint32_t addr) {
    asm volatile("ldmatrix.sync.aligned.m8n8.x4.shared.b16 {%0,%1,%2,%3}, [%4];"
                 : "=r"(r[0]), "=r"(r[1]), "=r"(r[2]), "=r"(r[3]) : "r"(addr));
}

// ---------------------------------------------------------------------------
// Merged prepass: one launch converts e_t + all 4 W matrices to fp16 (RN).
// grid.y: 0 -> e_t (4x chunks), 1..4 -> W segments.
// ---------------------------------------------------------------------------
__global__ void f2h_all_kernel(const float4* __restrict__ eA,
                               const float4* __restrict__ w0,
                               const float4* __restrict__ w1,
                               const float4* __restrict__ w2,
                               const float4* __restrict__ w3,
                               __half2* __restrict__ dA,
                               __half2* __restrict__ dW,
                               int n4w) {            // float4 count per W
    const int y = blockIdx.y;
    const float4* src;
    __half2* dst;
    int n4;
    if (y == 0) { src = eA; dst = dA; n4 = n4w * 4; }           // e_t = 4 W's
    else {
        src = (y == 1) ? w0 : (y == 2) ? w1 : (y == 3) ? w2 : w3;
        dst = dW + (size_t)(y - 1) * n4w * 2;
        n4 = n4w;
    }
    const int stride = gridDim.x * blockDim.x;
    for (int i = blockIdx.x * blockDim.x + threadIdx.x; i < n4; i += stride) {
        float4 v = src[i];
        dst[2 * i]     = __floats2half2_rn(v.x, v.y);
        dst[2 * i + 1] = __floats2half2_rn(v.z, v.w);
    }
}

// ---------------------------------------------------------------------------
// Fused GEMM + epilogue
// ---------------------------------------------------------------------------
__global__ void __launch_bounds__(NTHREADS, 2)
mipt_kernel(const __half* __restrict__ gA, const __half* __restrict__ gW,
            const float* __restrict__ h_prev,
            const float* __restrict__ b_p, const float* __restrict__ b_th,
            const float* __restrict__ b_r, const float* __restrict__ b_i,
            float* __restrict__ out) {
    extern __shared__ float sm[];
    const int tid = threadIdx.x;
    const int bx = blockIdx.x;
    const int mt = bx & 63;          // m-tile (64)
    const int nt = bx >> 6;          // n-tile (64; 32 cols per segment)
    const uint32_t sbase = smem_u32(sm);

    const int wid = tid >> 5, lane = tid & 31;
    const int g = lane >> 2, tg = lane & 3;
    const int wm = (wid & 3) * 32;   // warp m offset (4 m-warps)
    const int wn = (wid >> 2) * 64;  // warp n offset (2 n-warps)

    // ldmatrix per-lane base byte offsets (within a stage)
    const uint32_t aoff =
        (uint32_t)((wm + (lane & 15)) * ROWB) + ((uint32_t)(lane >> 4) << 4);
    const int rowB = wn + (lane & 7) + ((lane >> 4) << 3);
    const uint32_t boff =
        (uint32_t)(rowB * ROWB) + (((uint32_t)(lane >> 3) & 1u) << 4);

    // ---- async stage loader: A [128 x 64h] + B [128 x 64h] = 2048 chunks ----
    auto load_stage = [&](int s, int k0) {
        const uint32_t smA = sbase + s * STAGE_BYTES;
        #pragma unroll
        for (int r = 0; r < 8; r++) {
            const int ch = tid + r * NTHREADS;    // 0..2047
            const int row = ch >> 3, q = ch & 7;  // 8 x 16B chunks (8 halfs each)
            if (row < BM) {
                const __half* ga = gA + (size_t)(mt * 128 + row) * D_DIM + k0 + q * 8;
                cp_async16(smA + row * ROWB + q * 16, ga);
            } else {
                const int br = row - BM;          // 0..127
                const int j = br >> 5, c = br & 31;
                const __half* gb = gW + (size_t)j * (D_DIM * D_DIM)
                                      + (size_t)(nt * 32 + c) * D_DIM + k0 + q * 8;
                cp_async16(smA + STAGE_A_BYTES + br * ROWB + q * 16, gb);
            }
        }
        asm volatile("cp.async.commit_group;");
    };

    float acc[2][8][4] = {};          // [mi][ni][regs] : 32x64 warp tile
    uint32_t af[2][2][4];             // [buf][mi][regs] (double-buffered)
    uint32_t bf[2][4][4];             // [buf][nb][regs]

    load_stage(0, 0);
    load_stage(1, BK);

    // ---- L2-prefetch this CTA's epilogue inputs (h_prev slice + biases) ----
    {
        const int prow = tid >> 1;            // 0..127
        const int half = tid & 1;             // 0: re, 1: im
        prefetch_l2(h_prev + (size_t)(mt * 128 + prow) * (2 * D_DIM)
                    + (size_t)half * D_DIM + nt * 32);
        if (tid < 4) {
            const float* bsel = (tid == 0) ? b_p : (tid == 1) ? b_th
                              : (tid == 2) ? b_r : b_i;
            prefetch_l2(bsel + nt * 32);
        }
    }

    for (int it = 0; it < NITER; it++) {
        asm volatile("cp.async.wait_group %0;" :: "n"(STAGES - 2));
        __syncthreads();
        const int cs = it % STAGES;
        const uint32_t sA = sbase + (uint32_t)cs * STAGE_BYTES;
        const uint32_t sB = sA + STAGE_A_BYTES;

        // prefetch kk=0 fragments before the cp.async issue burst
        #pragma unroll
        for (int mi = 0; mi < 2; mi++)
            ldsm_x4(af[0][mi], sA + aoff + (uint32_t)mi * (16u * ROWB));
        #pragma unroll
        for (int nb = 0; nb < 4; nb++)
            ldsm_x4(bf[0][nb], sB + boff + (uint32_t)nb * (16u * ROWB));

        if (it + STAGES - 1 < NITER)
            load_stage((it + STAGES - 1) % STAGES, (it + STAGES - 1) * BK);

        #pragma unroll
        for (int kk = 0; kk < 4; kk++) {          // 4 x k16 per stage
            const int cur = kk & 1, nxt = cur ^ 1;
            if (kk < 3) {   // prefetch kk+1 fragments (+32B per k16 step)
                const uint32_t ko = (uint32_t)(kk + 1) * 32u;
                #pragma unroll
                for (int mi = 0; mi < 2; mi++)
                    ldsm_x4(af[nxt][mi],
                            sA + aoff + (uint32_t)mi * (16u * ROWB) + ko);
                #pragma unroll
                for (int nb = 0; nb < 4; nb++)
                    ldsm_x4(bf[nxt][nb],
                            sB + boff + (uint32_t)nb * (16u * ROWB) + ko);
            }
            #pragma unroll
            for (int mi = 0; mi < 2; mi++)
                #pragma unroll
                for (int nb = 0; nb < 4; nb++) {
                    mma_f16(acc[mi][2 * nb],     af[cur][mi], &bf[cur][nb][0]);
                    mma_f16(acc[mi][2 * nb + 1], af[cur][mi], &bf[cur][nb][2]);
                }
        }
    }

    // ---- stage accumulators through smem: thread gathers (p,th,re,im) ----
    asm volatile("cp.async.wait_group 0;");
    __syncthreads();
    float* epi = sm;   // 128 x EPI_STRIDE (67.6 KB <= SMEM_MAIN)
    #pragma unroll
    for (int mi = 0; mi < 2; mi++)
        #pragma unroll
        for (int ni = 0; ni < 8; ni++) {
            const int r = wm + mi * 16 + g;
            const int n = wn + ni * 8 + 2 * tg;
            epi[r * EPI_STRIDE + n]           = acc[mi][ni][0];
            epi[r * EPI_STRIDE + n + 1]       = acc[mi][ni][1];
            epi[(r + 8) * EPI_STRIDE + n]     = acc[mi][ni][2];
            epi[(r + 8) * EPI_STRIDE + n + 1] = acc[mi][ni][3];
        }
    __syncthreads();

    // ---- fused epilogue: sigmoid gate + rotation + blend ----
    const int rowt = tid >> 3;            // 0..31
    const int cb = (tid & 7) * 4;         // 0..28
    const int ng = nt * 32 + cb;
    const float4 bp = *(const float4*)&b_p[ng];
    const float4 bt = *(const float4*)&b_th[ng];
    const float4 br = *(const float4*)&b_r[ng];
    const float4 bi = *(const float4*)&b_i[ng];

    #pragma unroll
    for (int rep = 0; rep < 4; rep++) {
        const int m = rep * 32 + rowt;
        const size_t gm = (size_t)(mt * 128 + m);
        const float4 pl = *(const float4*)&epi[m * EPI_STRIDE + 0 * 32 + cb];
        const float4 th = *(const float4*)&epi[m * EPI_STRIDE + 1 * 32 + cb];
        const float4 xr = *(const float4*)&epi[m * EPI_STRIDE + 2 * 32 + cb];
        const float4 xi = *(const float4*)&epi[m * EPI_STRIDE + 3 * 32 + cb];
        const float4 hr = *(const float4*)&h_prev[gm * (2 * D_DIM) + ng];
        const float4 hi = *(const float4*)&h_prev[gm * (2 * D_DIM) + D_DIM + ng];

        float plv[4] = {pl.x + bp.x, pl.y + bp.y, pl.z + bp.z, pl.w + bp.w};
        float thv[4] = {th.x + bt.x, th.y + bt.y, th.z + bt.z, th.w + bt.w};
        float xrv[4] = {xr.x + br.x, xr.y + br.y, xr.z + br.z, xr.w + br.w};
        float xiv[4] = {xi.x + bi.x, xi.y + bi.y, xi.z + bi.z, xi.w + bi.w};
        float hrv[4] = {hr.x, hr.y, hr.z, hr.w};
        float hiv[4] = {hi.x, hi.y, hi.z, hi.w};
        float ore[4], oim[4];
        #pragma unroll
        for (int c = 0; c < 4; c++) {
            const float p = 1.0f / (1.0f + __expf(-plv[c]));
            float sn, cs;
            __sincosf(thv[c], &sn, &cs);
            const float rre = cs * hrv[c] - sn * hiv[c];
            const float rim = sn * hrv[c] + cs * hiv[c];
            ore[c] = rre + p * (xrv[c] - rre);
            oim[c] = rim + p * (xiv[c] - rim);
        }
        *(float4*)&out[gm * (2 * D_DIM) + ng] =
            make_float4(ore[0], ore[1], ore[2], ore[3]);
        *(float4*)&out[gm * (2 * D_DIM) + D_DIM + ng] =
            make_float4(oim[0], oim[1], oim[2], oim[3]);
    }
}

// ---------------------------------------------------------------------------
// Host
// ---------------------------------------------------------------------------
extern "C" void kernel_launch(void* const* d_in, const int* in_sizes, int n_in,
                              void* d_out, int out_size) {
    const float* e_t    = (const float*)d_in[0];
    const float* h_prev = (const float*)d_in[1];
    const float* W_p    = (const float*)d_in[2];
    const float* b_p    = (const float*)d_in[3];
    const float* W_th   = (const float*)d_in[4];
    const float* b_th   = (const float*)d_in[5];
    const float* W_r    = (const float*)d_in[6];
    const float* b_r    = (const float*)d_in[7];
    const float* W_i    = (const float*)d_in[8];
    const float* b_i    = (const float*)d_in[9];
    float* out = (float*)d_out;

    __half* sA = nullptr; __half* sW = nullptr;
    cudaGetSymbolAddress((void**)&sA, g_Ah);
    cudaGetSymbolAddress((void**)&sW, g_Wh);

    const size_t nW = (size_t)D_DIM * D_DIM;
    // one launch converts everything: y=0 e_t, y=1..4 the W segments
    f2h_all_kernel<<<dim3(640, 5), 256>>>(
        (const float4*)e_t, (const float4*)W_p, (const float4*)W_th,
        (const float4*)W_r, (const float4*)W_i,
        (__half2*)sA, (__half2*)sW, (int)(nW / 4));

    cudaFuncSetAttribute(mipt_kernel, cudaFuncAttributeMaxDynamicSharedMemorySize,
                         SMEM_MAIN);
    // grid: nt-major so a wave shares W tiles; A stays L2-resident
    mipt_kernel<<<64 * 64, NTHREADS, SMEM_MAIN>>>(sA, sW, h_prev,
                                                  b_p, b_th, b_r, b_i, out);
}